// round 17
// baseline (speedup 1.0000x reference)
#include <cuda_runtime.h>
#include <cstdint>

// Problem dims (fixed by setup_inputs)
#define B_ 512
#define N_ 2048   // OUT
#define K_ 2048   // IN
#define NSTEPS 16
// PROVEN (R11, rel_err = 0.0): reference association = fp32, K split in 4
// quarters of 512; each quarter a continuous ascending FFMA chain from zero;
// quarter-partials folded sequentially (one RN add each, ascending order).
#define KC 512
#define NSLICE (K_ / KC)   // 4
#define SZ (B_ * N_)

// GEMM tiling
#define BM 128
#define BN 128
#define BK 32
#define NT (KC / BK)       // 16 k-tiles per slice
#define STRA 264           // duplicated-A smem row stride (floats)
#define STRB 132           // B smem row stride (floats)
#define A_BUF (BK * STRA)  // floats per A buffer
#define B_BUF (BK * STRB)
#define SMEM_GEMM ((2 * A_BUF + 2 * B_BUF) * 4)   // 101376 B

// Scratch (static __device__: no allocation allowed)
__device__ float g_WrT[(size_t)N_ * N_];   // (W_rec*mask)^T [k][n]
__device__ float g_WfcT[(size_t)K_ * N_];  // W_fc^T [k][n]
__device__ float g_xT[(size_t)K_ * B_];    // x^T [k][m]
__device__ float g_spkT[(size_t)N_ * B_];  // spk^T [k][m] (GEMM A operand)
__device__ float g_part[(size_t)NSLICE * SZ];  // split-K partials (16MB)
__device__ float g_ff[SZ];
__device__ float g_mem[SZ];
__device__ float g_ath[SZ];
__device__ float g_spk[SZ];                // row-major spikes (state)

// ---------------------------------------------------------------------------
// Packed f32x2 helpers (each lane is an exact IEEE RN FMA == __fmaf_rn;
// per-output association unchanged)
// ---------------------------------------------------------------------------
static __device__ __forceinline__ void ffma2(unsigned long long& d,
                                             unsigned long long a,
                                             unsigned long long b) {
    asm("fma.rn.f32x2 %0, %1, %2, %0;" : "+l"(d) : "l"(a), "l"(b));
}
static __device__ __forceinline__ void unpack2(unsigned long long v,
                                               float& lo, float& hi) {
    asm("mov.b64 {%0, %1}, %2;" : "=f"(lo), "=f"(hi) : "l"(v));
}

// ---------------------------------------------------------------------------
// Transpose (optionally fused with integer mask multiply)
// ---------------------------------------------------------------------------
__global__ void transpose_mask_kernel(const float* __restrict__ src,
                                      const int* __restrict__ mask,
                                      float* __restrict__ dst, int R, int C) {
    __shared__ float tile[32][33];
    int c0 = blockIdx.x * 32, r0 = blockIdx.y * 32;
#pragma unroll
    for (int i = 0; i < 32; i += 8) {
        int r = r0 + threadIdx.y + i;
        int c = c0 + threadIdx.x;
        float v = src[(size_t)r * C + c];
        if (mask) v *= (float)mask[(size_t)r * C + c];
        tile[threadIdx.y + i][threadIdx.x] = v;
    }
    __syncthreads();
#pragma unroll
    for (int i = 0; i < 32; i += 8) {
        int r = c0 + threadIdx.y + i;
        int c = r0 + threadIdx.x;
        dst[(size_t)r * R + c] = tile[threadIdx.x][threadIdx.y + i];
    }
}

__global__ void init_zero_kernel(float* __restrict__ out) {
    int i = blockIdx.x * blockDim.x + threadIdx.x;
    if (i < SZ) {
        g_mem[i] = 0.0f;
        g_ath[i] = 0.0f;
        g_spk[i] = 0.0f;
        out[i]   = 0.0f;
    }
}

// ---------------------------------------------------------------------------
// cp.async helpers (B operand only)
// ---------------------------------------------------------------------------
static __device__ __forceinline__ void cpa16(uint32_t dst, const float* src) {
    asm volatile("cp.async.cg.shared.global [%0], [%1], 16;"
                 :: "r"(dst), "l"(src));
}
static __device__ __forceinline__ void cpa_commit() {
    asm volatile("cp.async.commit_group;" ::: "memory");
}

// ---------------------------------------------------------------------------
// Split-K slice SGEMM (operands pre-transposed to [k][.]):
//   part(m,n,z) = FMA chain over k ascending in [z*512,(z+1)*512) from zero.
// BM=BN=128, BK=32, 8x8/thread via packed f32x2 (32 FFMA2/kk), 256 threads,
// grid (16,4,4)=256 CTAs, 2 CTAs/SM.
// A staged DUPLICATED in smem (As2[k][2m]=As2[k][2m+1]=a[m]) so FFMA2 a-pairs
// come straight from LDS.128 — zero broadcast MOVs in the inner loop.
// A: register-prefetch + dup STS; B: cp.async double-buffer.
// ---------------------------------------------------------------------------
__global__ void __launch_bounds__(256, 2)
slice_gemm(const float* __restrict__ AT, const float* __restrict__ BT,
           const int* __restrict__ sw, int step) {
    if (step >= *sw) return;   // uniform

    extern __shared__ float sm[];
    const uint32_t smb = (uint32_t)__cvta_generic_to_shared(sm);
    const int tid = threadIdx.x;
    const int wid = tid >> 5;
    const int lane = tid & 31;
    const int lm = lane & 7;
    const int ln = lane >> 3;
    const int wm = (wid & 1) * 64;
    const int wn = (wid >> 1) * 32;
    const int bm = blockIdx.y * BM;
    const int bn = blockIdx.x * BN;
    const int z  = blockIdx.z;
    const int kbase = z * KC;

    const int m0 = wm + lm * 4, m1 = m0 + 32;
    const int n0 = wn + ln * 4, n1 = n0 + 16;

    // packed accumulators: [mi][ni][i][jp], lanes = (col 2*jp, col 2*jp+1)
    unsigned long long acc2[2][2][4][2];
#pragma unroll
    for (int mi = 0; mi < 2; mi++)
#pragma unroll
        for (int ni = 0; ni < 2; ni++)
#pragma unroll
            for (int i = 0; i < 4; i++)
#pragma unroll
                for (int jp = 0; jp < 2; jp++) acc2[mi][ni][i][jp] = 0ull;

    // staging mappings: 1024 16B-chunks per tile per operand; 4 per thread
    const float* srcA[4];
    const float* srcB[4];
    uint32_t dA[4], dB[4];
#pragma unroll
    for (int f = 0; f < 4; f++) {
        const int id = tid + 256 * f;
        const int k = id >> 5;              // 0..31
        const int c4 = (id & 31) << 2;      // 0..124
        srcA[f] = AT + (size_t)(kbase + k) * B_ + bm + c4;
        srcB[f] = BT + (size_t)(kbase + k) * N_ + bn + c4;
        dA[f] = smb + (uint32_t)(k * STRA + 2 * c4) * 4u;            // dup dest
        dB[f] = smb + (uint32_t)(2 * A_BUF + k * STRB + c4) * 4u;
    }

    // prologue: prefetch A tile0 into regs; cp.async B tile0 into buf 0
    float4 av[4];
#pragma unroll
    for (int f = 0; f < 4; f++) av[f] = *(const float4*)(srcA[f]);
#pragma unroll
    for (int f = 0; f < 4; f++) cpa16(dB[f], srcB[f]);
    cpa_commit();

    for (int t = 0; t < NT; t++) {
        const int buf = t & 1;
        const uint32_t aoff = (uint32_t)(buf * A_BUF * 4);
        // stage A[t] duplicated: value at col c -> smem cols 2c, 2c+1
#pragma unroll
        for (int f = 0; f < 4; f++) {
            float4 lo = { av[f].x, av[f].x, av[f].y, av[f].y };
            float4 hi = { av[f].z, av[f].z, av[f].w, av[f].w };
            asm volatile("st.shared.v4.f32 [%0], {%1,%2,%3,%4};"
                         :: "r"(dA[f] + aoff), "f"(lo.x), "f"(lo.y),
                            "f"(lo.z), "f"(lo.w));
            asm volatile("st.shared.v4.f32 [%0], {%1,%2,%3,%4};"
                         :: "r"(dA[f] + aoff + 16), "f"(hi.x), "f"(hi.y),
                            "f"(hi.z), "f"(hi.w));
        }
        if (t + 1 < NT) {
            const uint32_t bo = (uint32_t)(((t + 1) & 1) * B_BUF * 4);
            const size_t koB = (size_t)(t + 1) * BK * N_;
#pragma unroll
            for (int f = 0; f < 4; f++) cpa16(dB[f] + bo, srcB[f] + koB);
            cpa_commit();
            asm volatile("cp.async.wait_group 1;" ::: "memory");
        } else {
            asm volatile("cp.async.wait_group 0;" ::: "memory");
        }
        __syncthreads();

        // prefetch A[t+1] into regs (overlapped with compute)
        if (t + 1 < NT) {
            const size_t koA = (size_t)(t + 1) * BK * B_;
#pragma unroll
            for (int f = 0; f < 4; f++)
                av[f] = *(const float4*)(srcA[f] + koA);
        }

        const float* as = sm + buf * A_BUF;
        const float* bs = sm + 2 * A_BUF + buf * B_BUF;
#pragma unroll 8
        for (int kk = 0; kk < BK; kk++) {
            // a pairs {a,a} straight from duplicated smem (no MOVs)
            const ulonglong2 a00 = *(const ulonglong2*)&as[kk * STRA + 2 * m0];
            const ulonglong2 a01 = *(const ulonglong2*)&as[kk * STRA + 2 * m0 + 4];
            const ulonglong2 a10 = *(const ulonglong2*)&as[kk * STRA + 2 * m1];
            const ulonglong2 a11 = *(const ulonglong2*)&as[kk * STRA + 2 * m1 + 4];
            const unsigned long long ap[2][4] = {
                { a00.x, a00.y, a01.x, a01.y },
                { a10.x, a10.y, a11.x, a11.y } };
            const unsigned long long* bq0 =
                (const unsigned long long*)&bs[kk * STRB + n0];
            const unsigned long long* bq1 =
                (const unsigned long long*)&bs[kk * STRB + n1];
            const unsigned long long bp[2][2] = { { bq0[0], bq0[1] },
                                                  { bq1[0], bq1[1] } };
#pragma unroll
            for (int mi = 0; mi < 2; mi++)
#pragma unroll
                for (int ni = 0; ni < 2; ni++)
#pragma unroll
                    for (int i = 0; i < 4; i++)
#pragma unroll
                        for (int jp = 0; jp < 2; jp++)
                            ffma2(acc2[mi][ni][i][jp], ap[mi][i], bp[ni][jp]);
        }
        __syncthreads();   // protect buffers before restage at t+1
    }

    float* Pz = g_part + (size_t)z * SZ;
#pragma unroll
    for (int mi = 0; mi < 2; mi++) {
#pragma unroll
        for (int i = 0; i < 4; i++) {
            const int row = bm + wm + mi * 32 + lm * 4 + i;
#pragma unroll
            for (int ni = 0; ni < 2; ni++) {
                const int col = bn + wn + ni * 16 + ln * 4;
                float4 v;
                unpack2(acc2[mi][ni][i][0], v.x, v.y);
                unpack2(acc2[mi][ni][i][1], v.z, v.w);
                *(float4*)&Pz[(size_t)row * N_ + col] = v;
            }
        }
    }
}

// ---------------------------------------------------------------------------
// ff reduce: fold partials (ascending RN, exact R11 sequence) + bias -> g_ff
// ---------------------------------------------------------------------------
__global__ void __launch_bounds__(256)
reduce_ff(const float* __restrict__ bias) {
    const int i = blockIdx.x * blockDim.x + threadIdx.x;
    if (i >= SZ) return;
    float acc = 0.0f;
#pragma unroll
    for (int zz = 0; zz < NSLICE; zz++)
        acc = __fadd_rn(acc, g_part[(size_t)zz * SZ + i]);
    g_ff[i] = __fadd_rn(acc, bias[i & (N_ - 1)]);
}

// ---------------------------------------------------------------------------
// SNN step reduce: fold partials + bias -> mem_r, full state update (per-op
// RN), write spk row-major AND transposed (via smem tile) for next GEMM.
// ZACC=true: partials are exactly zero (t=0, spk==0) — skip reads.
// ---------------------------------------------------------------------------
template <bool ZACC>
__global__ void __launch_bounds__(256)
reduce_snn(const float* __restrict__ bias, float* __restrict__ ssum,
           const int* __restrict__ sw, int step) {
    if (step >= *sw) return;
    __shared__ float tile[32][33];
    const int n0 = blockIdx.x * 32, m0 = blockIdx.y * 32;
    const int tx = threadIdx.x & 31, ty = threadIdx.x >> 5;   // ty 0..7
    const float b = bias[n0 + tx];
#pragma unroll
    for (int r = 0; r < 4; r++) {
        const int ml = ty + 8 * r;
        const size_t i = (size_t)(m0 + ml) * N_ + n0 + tx;
        float acc = 0.0f;
        if (!ZACC) {
#pragma unroll
            for (int zz = 0; zz < NSLICE; zz++)
                acc = __fadd_rn(acc, g_part[(size_t)zz * SZ + i]);
        }
        const float mr = __fadd_rn(acc, b);
        float s = g_spk[i];
        float m = g_mem[i];
        float a = g_ath[i];
        a = __fadd_rn(__fmul_rn(0.9f, a), __fmul_rn(0.5f, s));
        float mff = __fmul_rn(m, 0.2f);
        mff = __fmul_rn(mff, __fsub_rn(1.0f, s));
        mff = __fadd_rn(mff, g_ff[i]);
        mff = __fsub_rn(mff, __fmul_rn(a, 0.2f));
        const float sff = (mff > 0.5f) ? 1.0f : 0.0f;
        const float sr  = (mr  > 0.5f) ? 1.0f : 0.0f;
        g_mem[i] = __fadd_rn(mff, mr);
        g_ath[i] = a;
        const float sn = __fadd_rn(sff, sr);
        g_spk[i] = sn;
        ssum[i] = __fadd_rn(ssum[i], sn);
        tile[ml][tx] = sn;
    }
    __syncthreads();
#pragma unroll
    for (int r = 0; r < 4; r++) {
        const int nl = ty + 8 * r;
        g_spkT[(size_t)(n0 + nl) * B_ + m0 + tx] = tile[tx][nl];
    }
}

// ---------------------------------------------------------------------------
// Launch. Inputs: x, W_fc, b_fc, W_rec, b_rec, rec_mask, spike_window
// ---------------------------------------------------------------------------
extern "C" void kernel_launch(void* const* d_in, const int* in_sizes, int n_in,
                              void* d_out, int out_size) {
    const float* x        = (const float*)d_in[0];
    const float* W_fc     = (const float*)d_in[1];
    const float* b_fc     = (const float*)d_in[2];
    const float* W_rec    = (const float*)d_in[3];
    const float* b_rec    = (const float*)d_in[4];
    const int*   rec_mask = (const int*)d_in[5];
    const int*   sw       = (const int*)d_in[6];
    float*       out      = (float*)d_out;

    float *WrT, *WfcT, *xT, *spkT;
    cudaGetSymbolAddress((void**)&WrT,  g_WrT);
    cudaGetSymbolAddress((void**)&WfcT, g_WfcT);
    cudaGetSymbolAddress((void**)&xT,   g_xT);
    cudaGetSymbolAddress((void**)&spkT, g_spkT);

    static int smem_set = 0;
    if (!smem_set) {
        cudaFuncSetAttribute(slice_gemm,
                             cudaFuncAttributeMaxDynamicSharedMemorySize,
                             SMEM_GEMM);
        smem_set = 1;
    }

    dim3 tt(32, 8);
    transpose_mask_kernel<<<dim3(K_ / 32, N_ / 32), tt>>>(W_fc, nullptr, WfcT, N_, K_);
    transpose_mask_kernel<<<dim3(N_ / 32, N_ / 32), tt>>>(W_rec, rec_mask, WrT, N_, N_);
    transpose_mask_kernel<<<dim3(K_ / 32, B_ / 32), tt>>>(x, nullptr, xT, B_, K_);

    init_zero_kernel<<<(SZ + 255) / 256, 256>>>(out);

    dim3 gg(N_ / BN, B_ / BM, NSLICE);        // (16, 4, 4) = 256 CTAs
    dim3 rg(N_ / 32, B_ / 32);                // (64, 16) reduce tiles

    // ff = x @ W_fc^T + b_fc  (loop-invariant)
    slice_gemm<<<gg, 256, SMEM_GEMM>>>(xT, WfcT, sw, -1);
    reduce_ff<<<(SZ + 255) / 256, 256>>>(b_fc);

    // t = 0: spk == 0 -> every chain is exactly 0.0; skip the GEMM.
    reduce_snn<true><<<rg, 256>>>(b_rec, out, sw, 0);

    // t = 1..15: split-K GEMM on spk^T + fused reduce/SNN
    for (int t = 1; t < NSTEPS; t++) {
        slice_gemm<<<gg, 256, SMEM_GEMM>>>(spkT, WrT, sw, t);
        reduce_snn<false><<<rg, 256>>>(b_rec, out, sw, t);
    }
}